// round 16
// baseline (speedup 1.0000x reference)
#include <cuda_runtime.h>
#include <cuda_fp16.h>
#include <cstdint>
#include <cstddef>

#define TOK 8192
#define DIN 4096
#define DOUT 4096
#define RANK 16
#define NBLK (DIN / 64)
#define K_EXT 4160            // DIN + 64 (16 lora cols + 1 bias col + pad)
#define SCALING 4.0f          // 16 / sqrt(16)

#define BM 128
#define BN 128
#define BK 64
#define NSTAGE 3
#define KITER (K_EXT / BK)    // 65

#define ROWB 144                             // 128B data + 16B pad; conflict-free ldmatrix
#define A_BYTES (BM * ROWB)                  // 18432
#define B_BYTES (BN * ROWB)                  // 18432
#define STAGE_BYTES (A_BYTES + B_BYTES)      // 36864
#define SMEM_TOTAL (NSTAGE * STAGE_BYTES)    // 110592 -> 2 CTAs/SM

#define NT_TILES (DOUT / BN)                 // 32
#define MT_TILES (TOK / BM)                  // 64
#define NTILES (MT_TILES * NT_TILES)         // 2048
#define GRID_P 296                           // 148 SMs x 2 CTAs, persistent

#define NXU (TOK / 32)                       // 256 xu blocks (32 rows each)

// Extended operand buffers (static device scratch; no runtime allocation)
__device__ __align__(1024) __half g_A[(size_t)TOK * K_EXT];   // ~68 MB
__device__ __align__(1024) __half g_B[(size_t)DOUT * K_EXT];  // ~34 MB

__constant__ float c_nf4[16] = {
    -1.0f, -0.6961928009986877f, -0.5250730514526367f, -0.39491748809814453f,
    -0.28444138169288635f, -0.18477343022823334f, -0.09105003625154495f, 0.0f,
    0.07958029955625534f, 0.16093020141124725f, 0.24611230194568634f,
    0.33791524171829224f, 0.44070982933044434f, 0.5626170039176941f,
    0.7229568362236023f, 1.0f};

// ---------------------------------------------------------------- helpers
__device__ __forceinline__ uint32_t s2u(const void* p) {
    uint32_t a;
    asm("{ .reg .u64 t; cvta.to.shared.u64 t, %1; cvt.u32.u64 %0, t; }"
        : "=r"(a) : "l"(p));
    return a;
}
__device__ __forceinline__ void cp16(uint32_t s, const void* g) {
    asm volatile("cp.async.cg.shared.global [%0], [%1], 16;" :: "r"(s), "l"(g));
}
__device__ __forceinline__ void cp_commit() {
    asm volatile("cp.async.commit_group;" ::: "memory");
}
__device__ __forceinline__ void ldsm4(uint32_t addr, uint32_t& r0, uint32_t& r1,
                                      uint32_t& r2, uint32_t& r3) {
    asm volatile("ldmatrix.sync.aligned.m8n8.x4.shared.b16 {%0,%1,%2,%3}, [%4];"
                 : "=r"(r0), "=r"(r1), "=r"(r2), "=r"(r3) : "r"(addr));
}
__device__ __forceinline__ void mma16816(float* c, const uint32_t* a,
                                         const uint32_t* b) {
    asm volatile(
        "mma.sync.aligned.m16n8k16.row.col.f32.f16.f16.f32 "
        "{%0,%1,%2,%3}, {%4,%5,%6,%7}, {%8,%9}, {%0,%1,%2,%3};"
        : "+f"(c[0]), "+f"(c[1]), "+f"(c[2]), "+f"(c[3])
        : "r"(a[0]), "r"(a[1]), "r"(a[2]), "r"(a[3]), "r"(b[0]), "r"(b[1]));
}

// -------------------------------------------------------- fused prep kernel
// blocks [0, NXU): x -> fp16 g_A + u = x@lora_A (4 rows/warp, 32 rows/block).
// blocks [NXU, NXU + DOUT): NF4 dequant -> g_B (+ lora_B cols, bias, zeros)
__global__ void __launch_bounds__(256) prep_all(
    const float* __restrict__ x, const int* __restrict__ wc,
    const float* __restrict__ am, const float* __restrict__ bias,
    const float* __restrict__ la, const float* __restrict__ lb) {
    __shared__ float sA2[16][520];  // transposed lora_A chunk (~33 KB)
    int tid = threadIdx.x;
    int lane = tid & 31;

    if (blockIdx.x >= NXU) {
        // ---------------- prep_w path (ILP=4 hoisted loads) ----------------
        float lutv = c_nf4[lane & 15];
        int n = blockIdx.x - NXU;
        const int* wr = wc + (size_t)n * DIN;
        __half* br = g_B + (size_t)n * K_EXT;
        const float* amr = am + (size_t)n * NBLK;

        int4 c[4];
        float s[4];
#pragma unroll
        for (int i = 0; i < 4; i++) {
            int k4 = tid + i * 256;
            c[i] = ((const int4*)wr)[k4];
            s[i] = amr[(k4 * 4) >> 6];
        }
#pragma unroll
        for (int i = 0; i < 4; i++) {
            int k4 = tid + i * 256;
            float v0 = __shfl_sync(0xffffffffu, lutv, c[i].x & 15);
            float v1 = __shfl_sync(0xffffffffu, lutv, c[i].y & 15);
            float v2 = __shfl_sync(0xffffffffu, lutv, c[i].z & 15);
            float v3 = __shfl_sync(0xffffffffu, lutv, c[i].w & 15);
            __half2 h0 = __floats2half2_rn(v0 * s[i], v1 * s[i]);
            __half2 h1 = __floats2half2_rn(v2 * s[i], v3 * s[i]);
            ((__half2*)br)[k4 * 2] = h0;
            ((__half2*)br)[k4 * 2 + 1] = h1;
        }
        if (tid < RANK) br[DIN + tid] = __float2half(SCALING * lb[(size_t)tid * DOUT + n]);
        else if (tid == RANK) br[DIN + RANK] = __float2half(bias[n]);
        else if (tid < 64) br[DIN + tid] = __float2half(0.0f);
        return;
    }

    // ------------- prep_xu path: 32 rows/block, 4 rows per warp -------------
    int wid = tid >> 5;
    size_t m0 = (size_t)blockIdx.x * 32 + wid * 4;
    const float* xr[4];
    __half* ar[4];
#pragma unroll
    for (int r = 0; r < 4; r++) {
        xr[r] = x + (m0 + r) * DIN;
        ar[r] = g_A + (m0 + r) * K_EXT;
    }
    float acc[4][16];
#pragma unroll
    for (int r = 0; r < 4; r++)
#pragma unroll
        for (int q = 0; q < 16; q++) acc[r][q] = 0.0f;

    for (int kc = 0; kc < DIN; kc += 512) {
        __syncthreads();
        const float4* la4 = (const float4*)(la + (size_t)kc * 16);
        for (int i = tid; i < 2048; i += 256) {
            float4 v = la4[i];
            int kk = i >> 2, r0 = (i & 3) * 4;
            sA2[r0][kk] = v.x;
            sA2[r0 + 1][kk] = v.y;
            sA2[r0 + 2][kk] = v.z;
            sA2[r0 + 3][kk] = v.w;
        }
        __syncthreads();
#pragma unroll
        for (int ki = 0; ki < 4; ki++) {     // 4 quads of 128 k per 512-chunk
            int k = ki * 128 + lane * 4;
            float xs[4][4];
#pragma unroll
            for (int r = 0; r < 4; r++) {
                float4 v = *(const float4*)(xr[r] + kc + k);
                xs[r][0] = v.x; xs[r][1] = v.y; xs[r][2] = v.z; xs[r][3] = v.w;
                __half2 h0 = __floats2half2_rn(v.x, v.y);
                __half2 h1 = __floats2half2_rn(v.z, v.w);
                uint2 st;
                st.x = *(uint32_t*)&h0;
                st.y = *(uint32_t*)&h1;
                *(uint2*)(ar[r] + kc + k) = st;
            }
#pragma unroll
            for (int q = 0; q < 16; q++) {
                float4 pv = *(const float4*)&sA2[q][k];
#pragma unroll
                for (int r = 0; r < 4; r++)
                    acc[r][q] += xs[r][0] * pv.x + xs[r][1] * pv.y +
                                 xs[r][2] * pv.z + xs[r][3] * pv.w;
            }
        }
    }
#pragma unroll
    for (int r = 0; r < 4; r++)
#pragma unroll
        for (int q = 0; q < 16; q++) {
            acc[r][q] += __shfl_xor_sync(0xffffffffu, acc[r][q], 16);
            acc[r][q] += __shfl_xor_sync(0xffffffffu, acc[r][q], 8);
            acc[r][q] += __shfl_xor_sync(0xffffffffu, acc[r][q], 4);
            acc[r][q] += __shfl_xor_sync(0xffffffffu, acc[r][q], 2);
            acc[r][q] += __shfl_xor_sync(0xffffffffu, acc[r][q], 1);
        }
#pragma unroll
    for (int r = 0; r < 4; r++) {
        if (lane == 0) {
#pragma unroll
            for (int q = 0; q < 16; q++) ar[r][DIN + q] = __float2half(acc[r][q]);
        }
        ar[r][DIN + 16 + lane] = __float2half(lane == 0 ? 1.0f : 0.0f);
        if (lane < 16) ar[r][DIN + 48 + lane] = __float2half(0.0f);
    }
}

// -------------------------------------------------------- main GEMM
// Persistent grid: 296 CTAs (2/SM), each loops over ~7 tiles. After a tile's
// main loop (final rotated boundary's __syncthreads guarantees no further smem
// stage reads), the NEXT tile's stage-0/1 fills are issued, then the epilogue
// runs — STG burst hides the next prologue, next tile starts pipeline-full.
// Per-tile loop body identical to the R11/R14 best config (BK=64, 3 stages,
// rotated boundary, MMA-half interleave).
__global__ void __launch_bounds__(128, 2) qlora_gemm(float* __restrict__ out) {
    extern __shared__ char smem[];
    uint32_t sb = s2u(smem);
    int tid = threadIdx.x, wid = tid >> 5, lane = tid & 31;
    int warp_m = wid & 1, warp_n = wid >> 1;   // 2 x 2

    uint32_t dA0 = (uint32_t)(tid >> 3) * ROWB + (tid & 7) * 16;
    uint32_t dB0 = A_BYTES + dA0;
    uint32_t aLdBase = (warp_m * 64 + (lane & 15)) * ROWB + (lane >> 4) * 16;
    uint32_t bLdBase = A_BYTES +
        (warp_n * 64 + ((lane >> 4) & 1) * 8 + (lane & 7)) * ROWB +
        ((lane >> 3) & 1) * 16;

    // tile -> (mt, nt) with L2 banding: 8 m-tiles x 32 n-tiles per band
#define TILE_MT(t) ((((t) >> 8) << 3) + ((t) & 7))
#define TILE_NT(t) ((((t) & 255) >> 3))
#define TILE_PTRS(t)                                                           \
    sA0 = g_A + (size_t)TILE_MT(t) * BM * K_EXT +                              \
          (size_t)(tid >> 3) * K_EXT + (tid & 7) * 8;                          \
    sB0 = g_B + (size_t)TILE_NT(t) * BN * K_EXT +                              \
          (size_t)(tid >> 3) * K_EXT + (tid & 7) * 8;

    const __half *sA0, *sB0;

#define ISSUE_STAGE(stage, kiter)                                              \
    {                                                                          \
        uint32_t base_ = sb + (stage) * STAGE_BYTES;                           \
        int k0_ = (kiter) * BK;                                                \
        _Pragma("unroll")                                                      \
        for (int i = 0; i < 8; i++)                                            \
            cp16(base_ + dA0 + i * (16 * ROWB),                                \
                 sA0 + k0_ + (size_t)i * 16 * K_EXT);                          \
        _Pragma("unroll")                                                      \
        for (int i = 0; i < 8; i++)                                            \
            cp16(base_ + dB0 + i * (16 * ROWB),                                \
                 sB0 + k0_ + (size_t)i * 16 * K_EXT);                          \
    }

#define ISSUE_CHUNK(stage, kiter, ch)                                          \
    {                                                                          \
        uint32_t base_ = sb + (stage) * STAGE_BYTES;                           \
        int k0_ = (kiter) * BK;                                                \
        _Pragma("unroll")                                                      \
        for (int i = 2 * (ch); i < 2 * (ch) + 2; i++) {                        \
            cp16(base_ + dA0 + i * (16 * ROWB),                                \
                 sA0 + k0_ + (size_t)i * 16 * K_EXT);                          \
            cp16(base_ + dB0 + i * (16 * ROWB),                                \
                 sB0 + k0_ + (size_t)i * 16 * K_EXT);                          \
        }                                                                      \
    }

#define LOAD_FRAGS(buf, aB, bB, kOff)                                          \
    {                                                                          \
        _Pragma("unroll")                                                      \
        for (int mi = 0; mi < 4; mi++)                                         \
            ldsm4((aB) + mi * (16 * ROWB) + (kOff),                            \
                  a[buf][mi][0], a[buf][mi][1], a[buf][mi][2], a[buf][mi][3]); \
        _Pragma("unroll")                                                      \
        for (int nj = 0; nj < 4; nj++)                                         \
            ldsm4((bB) + nj * (16 * ROWB) + (kOff),                            \
                  b[buf][2 * nj][0], b[buf][2 * nj][1],                        \
                  b[buf][2 * nj + 1][0], b[buf][2 * nj + 1][1]);               \
    }

#define MMA_HALF(buf, h)                                                       \
    {                                                                          \
        _Pragma("unroll")                                                      \
        for (int mi = 2 * (h); mi < 2 * (h) + 2; mi++)                         \
            _Pragma("unroll")                                                  \
            for (int ni = 0; ni < 8; ni++)                                     \
                mma16816(acc[mi][ni], a[buf][mi], b[buf][ni]);                 \
    }

    int tile = (int)blockIdx.x;
    if (tile >= NTILES) return;

    // prologue for the first tile
    TILE_PTRS(tile);
    ISSUE_STAGE(0, 0); cp_commit();
    ISSUE_STAGE(1, 1); cp_commit();

    while (tile < NTILES) {
        float acc[4][8][4];
#pragma unroll
        for (int mi = 0; mi < 4; mi++)
#pragma unroll
            for (int ni = 0; ni < 8; ni++)
#pragma unroll
                for (int j = 0; j < 4; j++) acc[mi][ni][j] = 0.0f;

        uint32_t a[2][4][4], b[2][8][2];
        asm volatile("cp.async.wait_group %0;" :: "n"(1) : "memory");
        __syncthreads();
        LOAD_FRAGS(0, sb + aLdBase, sb + bLdBase, 0);

        int s = 0, sn = 2;
        for (int it = 0; it < KITER; ++it) {
            uint32_t aB = sb + s * STAGE_BYTES + aLdBase;
            uint32_t bB = sb + s * STAGE_BYTES + bLdBase;
            bool pf = (it + 2 < KITER);

#pragma unroll
            for (int kh = 0; kh < 4; kh++) {      // four k16 steps per BK=64
                int cur = kh & 1, nxb = cur ^ 1;
                if (kh < 3) {
                    LOAD_FRAGS(nxb, aB, bB, (kh + 1) * 32);
                    MMA_HALF(cur, 0);
                    if (pf) { ISSUE_CHUNK(sn, it + 2, kh); }
                    MMA_HALF(cur, 1);
                } else {
                    // rotated stage boundary under the final MMA block
                    if (pf) { ISSUE_CHUNK(sn, it + 2, 3); }
                    cp_commit();
                    asm volatile("cp.async.wait_group %0;" :: "n"(1) : "memory");
                    __syncthreads();
                    if (it + 1 < KITER) {
                        int s1 = (s == 2) ? 0 : s + 1;
                        uint32_t aB2 = sb + s1 * STAGE_BYTES + aLdBase;
                        uint32_t bB2 = sb + s1 * STAGE_BYTES + bLdBase;
                        LOAD_FRAGS(nxb, aB2, bB2, 0);   // nxb == 0 here
                    }
                    MMA_HALF(cur, 0);
                    MMA_HALF(cur, 1);
                }
            }

            s = (s == 2) ? 0 : s + 1;
            sn = (sn == 2) ? 0 : sn + 1;
        }

        // Current tile's output coords (before pointers advance)
        int mt = TILE_MT(tile), nt = TILE_NT(tile);

        // Cross-tile prefetch: all warps have passed the final boundary's
        // __syncthreads above -> no more smem stage reads this tile. Fill the
        // next tile's stages 0/1 now; the epilogue STG burst hides the latency.
        int ntile = tile + GRID_P;
        if (ntile < NTILES) {
            TILE_PTRS(ntile);
            ISSUE_STAGE(0, 0); cp_commit();
            ISSUE_STAGE(1, 1); cp_commit();
        }

        // ---- epilogue: registers -> global fp32 ----
        int m0 = mt * BM + warp_m * 64 + (lane >> 2);
        int n0 = nt * BN + warp_n * 64 + (lane & 3) * 2;
#pragma unroll
        for (int mi = 0; mi < 4; mi++) {
#pragma unroll
            for (int ni = 0; ni < 8; ni++) {
                float* p0 = out + (size_t)(m0 + mi * 16) * DOUT + n0 + ni * 8;
                float* p1 = p0 + 8 * DOUT;
                *(float2*)p0 = make_float2(acc[mi][ni][0], acc[mi][ni][1]);
                *(float2*)p1 = make_float2(acc[mi][ni][2], acc[mi][ni][3]);
            }
        }

        tile = ntile;
    }
}

// -------------------------------------------------------- launch
extern "C" void kernel_launch(void* const* d_in, const int* in_sizes, int n_in,
                              void* d_out, int out_size) {
    const float* x = (const float*)d_in[0];
    const int* wc = (const int*)d_in[1];
    const float* am = (const float*)d_in[2];
    const float* bias = (const float*)d_in[3];
    const float* la = (const float*)d_in[4];
    const float* lb = (const float*)d_in[5];
    float* out = (float*)d_out;

    cudaFuncSetAttribute(qlora_gemm, cudaFuncAttributeMaxDynamicSharedMemorySize,
                         SMEM_TOTAL);

    prep_all<<<NXU + DOUT, 256>>>(x, wc, am, bias, la, lb);
    qlora_gemm<<<GRID_P, 128, SMEM_TOTAL>>>(out);
}